// round 4
// baseline (speedup 1.0000x reference)
#include <cuda_runtime.h>
#include <cuda_bf16.h>
#include <cstdint>

// ---- problem constants ----
#define BDIM 4
#define TDIM 4096
#define NTOK (BDIM * TDIM)      // 16384
#define DDIM 2048
#define KDIM 2048               // H*2*E
#define TS 100000
#define VOCAB 50257
#define M0 20011
#define M1 30011
#define M2 40009

// ---- device scratch (allocation-free rule) ----
// two-level int8 quantization planes + per-row scales
__device__ int8_t g_ea0[(size_t)NTOK * KDIM];
__device__ int8_t g_ea1[(size_t)NTOK * KDIM];
__device__ int8_t g_wb0[(size_t)DDIM * KDIM];
__device__ int8_t g_wb1[(size_t)DDIM * KDIM];
__device__ float  g_sa[NTOK];
__device__ float  g_sb[DDIM];
__device__ float  g_v[(size_t)NTOK * DDIM];

// ============================================================================
// Baseline-PTX helpers (NO tcgen05 — harness compiles for plain sm_103)
// ============================================================================
__device__ __forceinline__ uint32_t smem_to_u32(const void* p) {
    uint32_t a;
    asm("{ .reg .u64 t; cvta.to.shared.u64 t, %1; cvt.u32.u64 %0, t; }"
        : "=r"(a) : "l"(p));
    return a;
}
__device__ __forceinline__ void cp_async16(uint32_t smem_addr, const void* gptr) {
    asm volatile("cp.async.cg.shared.global [%0], [%1], 16;"
                 :: "r"(smem_addr), "l"(gptr) : "memory");
}
__device__ __forceinline__ void cp_commit() {
    asm volatile("cp.async.commit_group;" ::: "memory");
}
template <int N>
__device__ __forceinline__ void cp_wait_group() {
    asm volatile("cp.async.wait_group %0;" :: "n"(N) : "memory");
}
__device__ __forceinline__ void ldsm_x4(uint32_t* r, uint32_t addr) {
    asm volatile("ldmatrix.sync.aligned.m8n8.x4.shared.b16 {%0,%1,%2,%3}, [%4];"
                 : "=r"(r[0]), "=r"(r[1]), "=r"(r[2]), "=r"(r[3]) : "r"(addr));
}
// D(s32) += A(s8,m16k32,row) * B(s8,k32n8,col)
__device__ __forceinline__ void mma_s8(int* d, const uint32_t* a,
                                       uint32_t b0, uint32_t b1) {
    asm volatile(
        "mma.sync.aligned.m16n8k32.row.col.s32.s8.s8.s32 "
        "{%0,%1,%2,%3}, {%4,%5,%6,%7}, {%8,%9}, {%0,%1,%2,%3};"
        : "+r"(d[0]), "+r"(d[1]), "+r"(d[2]), "+r"(d[3])
        : "r"(a[0]), "r"(a[1]), "r"(a[2]), "r"(a[3]), "r"(b0), "r"(b1));
}

// pack 8 signed chars -> uint2
union Pack8 { signed char b[8]; uint2 u; };

// quantize 8 floats with 2-level int8 given scale sa; write both planes
__device__ __forceinline__ void quant8_store(const float* xs, float sa,
                                             int8_t* p0, int8_t* p1) {
    float inv  = 127.f / (sa * 127.f);      // = 1/sa (kept simple)
    float inv2 = inv * 128.f;
    Pack8 q0, q1;
    #pragma unroll
    for (int j = 0; j < 8; j++) {
        float qf = rintf(xs[j] * inv);
        qf = fminf(fmaxf(qf, -127.f), 127.f);
        float r = fmaf(-qf, sa, xs[j]);
        float q2f = rintf(r * inv2);
        q2f = fminf(fmaxf(q2f, -127.f), 127.f);
        q0.b[j] = (signed char)(int)qf;
        q1.b[j] = (signed char)(int)q2f;
    }
    *reinterpret_cast<uint2*>(p0) = q0.u;
    *reinterpret_cast<uint2*>(p1) = q1.u;
}

// ============================================================================
// Kernel 0: quantize Wv rows.  One block per output row d (2048 blocks).
// ============================================================================
__global__ __launch_bounds__(256) void wconv_kernel(const float* __restrict__ Wv)
{
    int row = blockIdx.x;
    int tid = threadIdx.x;
    const float* src = Wv + (size_t)row * KDIM + tid * 8;
    float4 x0 = *reinterpret_cast<const float4*>(src);
    float4 x1 = *reinterpret_cast<const float4*>(src + 4);
    float xs[8] = {x0.x, x0.y, x0.z, x0.w, x1.x, x1.y, x1.z, x1.w};

    float m = 0.f;
    #pragma unroll
    for (int j = 0; j < 8; j++) m = fmaxf(m, fabsf(xs[j]));
    #pragma unroll
    for (int o = 16; o > 0; o >>= 1) m = fmaxf(m, __shfl_xor_sync(0xffffffffu, m, o));
    __shared__ float s_max[8];
    __shared__ float s_sc;
    int warp = tid >> 5, lane = tid & 31;
    if (lane == 0) s_max[warp] = m;
    __syncthreads();
    if (tid == 0) {
        float g = 0.f;
        #pragma unroll
        for (int w = 0; w < 8; w++) g = fmaxf(g, s_max[w]);
        float sa = fmaxf(g, 1e-20f) * (1.f / 127.f);
        g_sb[row] = sa;
        s_sc = sa;
    }
    __syncthreads();
    size_t dst = (size_t)row * KDIM + tid * 8;
    quant8_store(xs, s_sc, g_wb0 + dst, g_wb1 + dst);
}

// ============================================================================
// Kernel 1: hash + gather + quantize e rows.  One block per token.
// ============================================================================
__global__ __launch_bounds__(256) void gather_kernel(
    const int* __restrict__ input_ids,
    const float* __restrict__ tables2,
    const float* __restrict__ tables3)
{
    int t = blockIdx.x;
    int tid = threadIdx.x;
    __shared__ int s_i2, s_i3;
    if (tid == 0) {
        int b = t / TDIM;
        int tt = t % TDIM;
        const int* row = input_ids + (size_t)b * TDIM;
        int id0 = row[tt];
        id0 = id0 < 0 ? 0 : (id0 > VOCAB - 1 ? VOCAB - 1 : id0);
        int s1 = 0, s2 = 0;
        if (tt >= 1) { s1 = row[tt - 1]; s1 = s1 < 0 ? 0 : (s1 > VOCAB - 1 ? VOCAB - 1 : s1); }
        if (tt >= 2) { s2 = row[tt - 2]; s2 = s2 < 0 ? 0 : (s2 > VOCAB - 1 ? VOCAB - 1 : s2); }
        int hash2 = (id0 * M0) ^ (s1 * M1);
        int hash3 = hash2 ^ (s2 * M2);
        int i2 = hash2 % TS; if (i2 < 0) i2 = 0;
        int i3 = hash3 % TS; if (i3 < 0) i3 = 0;
        s_i2 = i2; s_i3 = i3;
    }
    __syncthreads();
    int i2 = s_i2, i3 = s_i3;

    int f0 = tid * 8;
    int seg = f0 >> 8;
    int off = f0 & 255;
    const float* src = (seg < 4)
        ? tables2 + ((size_t)seg * TS + i2) * 256 + off
        : tables3 + ((size_t)(seg - 4) * TS + i3) * 256 + off;
    float4 x0 = *reinterpret_cast<const float4*>(src);
    float4 x1 = *reinterpret_cast<const float4*>(src + 4);
    float xs[8] = {x0.x, x0.y, x0.z, x0.w, x1.x, x1.y, x1.z, x1.w};

    float m = 0.f;
    #pragma unroll
    for (int j = 0; j < 8; j++) m = fmaxf(m, fabsf(xs[j]));
    #pragma unroll
    for (int o = 16; o > 0; o >>= 1) m = fmaxf(m, __shfl_xor_sync(0xffffffffu, m, o));
    __shared__ float s_max[8];
    __shared__ float s_sc;
    int warp = tid >> 5, lane = tid & 31;
    if (lane == 0) s_max[warp] = m;
    __syncthreads();
    if (tid == 0) {
        float g = 0.f;
        #pragma unroll
        for (int w = 0; w < 8; w++) g = fmaxf(g, s_max[w]);
        float sa = fmaxf(g, 1e-20f) * (1.f / 127.f);
        g_sa[t] = sa;
        s_sc = sa;
    }
    __syncthreads();
    size_t dst = (size_t)t * KDIM + f0;
    quant8_store(xs, s_sc, g_ea0 + dst, g_ea1 + dst);
}

// ============================================================================
// Kernel 2: two-level int8 GEMM via mma.sync.m16n8k32.s8, fp32 result.
//   C[m][n] = sa[m]*sb[n]*(acc_hi + acc_mid/128)
//   CTA tile 128x128, k-chunk 32, 4-stage cp.async pipeline.
// Stage (16KB): A @0: 128 rows x 64B (4x16B units: [q0 k0-15 | q0 k16-31 |
//   q1 k0-15 | q1 k16-31]); B @8192 same.  unit swizzle: c ^= (row>>1)&3.
// ============================================================================
#define NKC (KDIM / 32)          // 64 chunks
#define N_ST 4
#define ST_BYTES 16384
#define SC_OFF (N_ST * ST_BYTES) // 65536
#define GEMM_SMEM (SC_OFF + 1024)

__global__ __launch_bounds__(256, 1) void gemm_kernel()
{
    extern __shared__ char smem[];
    const uint32_t sbase = smem_to_u32(smem);
    const int tid = threadIdx.x;
    const int lane = tid & 31;
    const int wid = tid >> 5;
    const int warpM = wid & 1;
    const int warpN = wid >> 1;
    const int m0 = blockIdx.y * 128;
    const int n0 = blockIdx.x * 128;

    float* s_sa = reinterpret_cast<float*>(smem + SC_OFF);
    float* s_sb = s_sa + 128;
    if (tid < 128) s_sa[tid] = g_sa[m0 + tid];
    else           s_sb[tid - 128] = g_sb[n0 + tid - 128];

    // ---- cp.async mapping: 4 x 16B per thread per stage ----
    const int8_t* src[4];
    uint32_t dstoff[4];
    #pragma unroll
    for (int i = 0; i < 4; i++) {
        int g = tid + i * 256;             // 0..1023
        int isB = g >= 512;
        int gl = g & 511;
        int row = gl >> 2;                 // 0..127
        int c = gl & 3;                    // unit: lv*2 + half
        int lv = c >> 1, half = c & 1;
        const int8_t* base = isB ? (lv ? g_wb1 : g_wb0)
                                 : (lv ? g_ea1 : g_ea0);
        src[i] = base + (size_t)((isB ? n0 : m0) + row) * KDIM + half * 16;
        dstoff[i] = (isB ? 8192u : 0u) + (uint32_t)row * 64u
                  + (uint32_t)((c ^ ((row >> 1) & 3)) << 4);
    }

    // ---- ldmatrix smem offsets (within stage) ----
    uint32_t aoff[4][2];                   // [mf][lv]
    #pragma unroll
    for (int mf = 0; mf < 4; mf++)
        #pragma unroll
        for (int lv = 0; lv < 2; lv++) {
            int R = warpM * 64 + mf * 16 + (lane & 7) + ((lane >> 3) & 1) * 8;
            int c = lv * 2 + (lane >> 4);
            aoff[mf][lv] = (uint32_t)R * 64u + (uint32_t)((c ^ ((R >> 1) & 3)) << 4);
        }
    uint32_t boff[2][2];                   // [nfp][lv]
    #pragma unroll
    for (int nfp = 0; nfp < 2; nfp++)
        #pragma unroll
        for (int lv = 0; lv < 2; lv++) {
            int R = warpN * 32 + nfp * 16 + (lane & 7) + ((lane >> 4) & 1) * 8;
            int c = lv * 2 + ((lane >> 3) & 1);
            boff[nfp][lv] = 8192u + (uint32_t)R * 64u
                          + (uint32_t)((c ^ ((R >> 1) & 3)) << 4);
        }

    int acc_hi[4][4][4], acc_mid[4][4][4];
    #pragma unroll
    for (int mf = 0; mf < 4; mf++)
        #pragma unroll
        for (int nf = 0; nf < 4; nf++)
            #pragma unroll
            for (int q = 0; q < 4; q++) { acc_hi[mf][nf][q] = 0; acc_mid[mf][nf][q] = 0; }

    // ---- prologue: stages 0..2 ----
    #pragma unroll
    for (int st = 0; st < 3; st++) {
        uint32_t sb = sbase + st * ST_BYTES;
        #pragma unroll
        for (int i = 0; i < 4; i++)
            cp_async16(sb + dstoff[i], src[i] + st * 32);
        cp_commit();
    }

    for (int kt = 0; kt < NKC; kt++) {
        if (kt <= NKC - 3)      cp_wait_group<2>();
        else if (kt == NKC - 2) cp_wait_group<1>();
        else                    cp_wait_group<0>();
        __syncthreads();

        if (kt + 3 < NKC) {
            uint32_t sb = sbase + ((kt + 3) & 3) * ST_BYTES;
            #pragma unroll
            for (int i = 0; i < 4; i++)
                cp_async16(sb + dstoff[i], src[i] + (kt + 3) * 32);
            cp_commit();
        }

        const uint32_t sb = sbase + (kt & 3) * ST_BYTES;
        uint32_t a[2][4][4];
        uint32_t bf[2][2][4];
        #pragma unroll
        for (int lv = 0; lv < 2; lv++)
            #pragma unroll
            for (int mf = 0; mf < 4; mf++)
                ldsm_x4(a[lv][mf], sb + aoff[mf][lv]);
        #pragma unroll
        for (int lv = 0; lv < 2; lv++)
            #pragma unroll
            for (int nfp = 0; nfp < 2; nfp++)
                ldsm_x4(bf[lv][nfp], sb + boff[nfp][lv]);

        #pragma unroll
        for (int mf = 0; mf < 4; mf++)
            #pragma unroll
            for (int nfp = 0; nfp < 2; nfp++)
                #pragma unroll
                for (int sub = 0; sub < 2; sub++) {
                    const int nf = nfp * 2 + sub;
                    const uint32_t b0h = bf[0][nfp][sub * 2], b1h = bf[0][nfp][sub * 2 + 1];
                    const uint32_t b0l = bf[1][nfp][sub * 2], b1l = bf[1][nfp][sub * 2 + 1];
                    mma_s8(acc_hi[mf][nf],  a[0][mf], b0h, b1h);   // q*q
                    mma_s8(acc_mid[mf][nf], a[0][mf], b0l, b1l);   // q*q2
                    mma_s8(acc_mid[mf][nf], a[1][mf], b0h, b1h);   // q2*q
                }
    }

    // ---- epilogue ----
    const int grp = lane >> 2;
    const int q2c = (lane & 3) * 2;
    #pragma unroll
    for (int mf = 0; mf < 4; mf++) {
        int r = warpM * 64 + mf * 16 + grp;
        float sa0 = s_sa[r], sa1 = s_sa[r + 8];
        #pragma unroll
        for (int nf = 0; nf < 4; nf++) {
            int c = warpN * 32 + nf * 8 + q2c;
            float sb0 = s_sb[c], sb1 = s_sb[c + 1];
            const int* hi = acc_hi[mf][nf];
            const int* md = acc_mid[mf][nf];
            float f0 = ((float)hi[0] + (float)md[0] * 0.0078125f) * sa0 * sb0;
            float f1 = ((float)hi[1] + (float)md[1] * 0.0078125f) * sa0 * sb1;
            float f2 = ((float)hi[2] + (float)md[2] * 0.0078125f) * sa1 * sb0;
            float f3 = ((float)hi[3] + (float)md[3] * 0.0078125f) * sa1 * sb1;
            *reinterpret_cast<float2*>(g_v + (size_t)(m0 + r) * DDIM + n0 + c) =
                make_float2(f0, f1);
            *reinterpret_cast<float2*>(g_v + (size_t)(m0 + r + 8) * DDIM + n0 + c) =
                make_float2(f2, f3);
        }
    }
}

// ============================================================================
// Kernel 3: gating
// ============================================================================
__global__ __launch_bounds__(256) void gate_kernel(
    const float* __restrict__ hidden,
    const float* __restrict__ wh,
    const float* __restrict__ wv,
    float* __restrict__ out)
{
    int t = blockIdx.x;
    int tid = threadIdx.x;
    const float* h = hidden + (size_t)t * DDIM;
    const float* v = g_v + (size_t)t * DDIM;

    float4 v4[2];
    float shh = 0.f, svv = 0.f, shv = 0.f;
    #pragma unroll
    for (int r = 0; r < 2; r++) {
        int q = tid + r * 256;
        float4 h4  = *reinterpret_cast<const float4*>(h + (size_t)q * 4);
        float4 x4  = *reinterpret_cast<const float4*>(v + (size_t)q * 4);
        float4 wh4 = *reinterpret_cast<const float4*>(wh + (size_t)q * 4);
        float4 wv4 = *reinterpret_cast<const float4*>(wv + (size_t)q * 4);
        v4[r] = x4;
        shh += h4.x * h4.x + h4.y * h4.y + h4.z * h4.z + h4.w * h4.w;
        svv += x4.x * x4.x + x4.y * x4.y + x4.z * x4.z + x4.w * x4.w;
        shv += (h4.x * wh4.x) * (x4.x * wv4.x)
             + (h4.y * wh4.y) * (x4.y * wv4.y)
             + (h4.z * wh4.z) * (x4.z * wv4.z)
             + (h4.w * wh4.w) * (x4.w * wv4.w);
    }

    #pragma unroll
    for (int o = 16; o > 0; o >>= 1) {
        shh += __shfl_down_sync(0xffffffffu, shh, o);
        svv += __shfl_down_sync(0xffffffffu, svv, o);
        shv += __shfl_down_sync(0xffffffffu, shv, o);
    }
    __shared__ float s0[8], s1[8], s2[8];
    int warp = tid >> 5, lane = tid & 31;
    if (lane == 0) { s0[warp] = shh; s1[warp] = svv; s2[warp] = shv; }
    __syncthreads();
    float thh = 0.f, tvv = 0.f, thv = 0.f;
    #pragma unroll
    for (int w = 0; w < 8; w++) { thh += s0[w]; tvv += s1[w]; thv += s2[w]; }

    const float eps = 1.1920928955078125e-7f;
    float rh = rsqrtf(thh * (1.f / DDIM) + eps);
    float rv = rsqrtf(tvv * (1.f / DDIM) + eps);
    float gate = thv * rh * rv * (1.f / 45.254833995939045f);
    float ga = fabsf(gate);
    ga = fmaxf(ga, 1e-6f);
    float gs = copysignf(sqrtf(ga), gate);
    float sig = 1.f / (1.f + expf(-gs));

    float* o = out + (size_t)t * DDIM;
    #pragma unroll
    for (int r = 0; r < 2; r++) {
        int q = tid + r * 256;
        float4 x = v4[r];
        x.x *= sig; x.y *= sig; x.z *= sig; x.w *= sig;
        *reinterpret_cast<float4*>(o + (size_t)q * 4) = x;
    }
}

// ---------------------------------------------------------------------------
extern "C" void kernel_launch(void* const* d_in, const int* in_sizes, int n_in,
                              void* d_out, int out_size)
{
    const float* hidden  = (const float*)d_in[0];
    const float* tables2 = (const float*)d_in[1];
    const float* tables3 = (const float*)d_in[2];
    const float* Wv      = (const float*)d_in[3];
    const float* wh      = (const float*)d_in[4];
    const float* wv      = (const float*)d_in[5];
    const int*   ids     = (const int*)d_in[6];
    float* out = (float*)d_out;

    static bool attr_set = false;
    if (!attr_set) {
        cudaFuncSetAttribute(gemm_kernel,
                             cudaFuncAttributeMaxDynamicSharedMemorySize, GEMM_SMEM);
        attr_set = true;
    }

    wconv_kernel<<<DDIM, 256>>>(Wv);
    gather_kernel<<<NTOK, 256>>>(ids, tables2, tables3);

    dim3 grid(DDIM / 128, NTOK / 128);   // x = N tiles (share A within a wave)
    gemm_kernel<<<grid, 256, GEMM_SMEM>>>();

    gate_kernel<<<NTOK, 256>>>(hidden, wh, wv, out);
}

// round 5
// speedup vs baseline: 6.1101x; 6.1101x over previous
#include <cuda_runtime.h>
#include <cuda_fp16.h>
#include <cstdint>

// ---- problem constants ----
#define BDIM 4
#define TDIM 4096
#define NTOK (BDIM * TDIM)      // 16384
#define DDIM 2048
#define KDIM 2048               // H*2*E
#define TS 100000
#define VOCAB 50257
#define M0 20011
#define M1 30011
#define M2 40009

// ---- device scratch (allocation-free rule) ----
__device__ __half g_e[(size_t)NTOK * KDIM];
__device__ __half g_w[(size_t)DDIM * KDIM];
__device__ float  g_v[(size_t)NTOK * DDIM];

// ============================================================================
// Baseline-PTX helpers (NO tcgen05 — harness compiles plain sm_103)
// ============================================================================
__device__ __forceinline__ uint32_t smem_to_u32(const void* p) {
    uint32_t a;
    asm("{ .reg .u64 t; cvta.to.shared.u64 t, %1; cvt.u32.u64 %0, t; }"
        : "=r"(a) : "l"(p));
    return a;
}
__device__ __forceinline__ void cp_async16(uint32_t smem_addr, const void* gptr) {
    asm volatile("cp.async.cg.shared.global [%0], [%1], 16;"
                 :: "r"(smem_addr), "l"(gptr) : "memory");
}
__device__ __forceinline__ void cp_commit() {
    asm volatile("cp.async.commit_group;" ::: "memory");
}
template <int N>
__device__ __forceinline__ void cp_wait_group() {
    asm volatile("cp.async.wait_group %0;" :: "n"(N) : "memory");
}
__device__ __forceinline__ void ldsm_x4(uint32_t* r, uint32_t addr) {
    asm volatile("ldmatrix.sync.aligned.m8n8.x4.shared.b16 {%0,%1,%2,%3}, [%4];"
                 : "=r"(r[0]), "=r"(r[1]), "=r"(r[2]), "=r"(r[3]) : "r"(addr));
}
__device__ __forceinline__ void mma_f16(float* d, const uint32_t* a,
                                        uint32_t b0, uint32_t b1) {
    asm volatile(
        "mma.sync.aligned.m16n8k16.row.col.f32.f16.f16.f32 "
        "{%0,%1,%2,%3}, {%4,%5,%6,%7}, {%8,%9}, {%0,%1,%2,%3};"
        : "+f"(d[0]), "+f"(d[1]), "+f"(d[2]), "+f"(d[3])
        : "r"(a[0]), "r"(a[1]), "r"(a[2]), "r"(a[3]), "r"(b0), "r"(b1));
}

// ============================================================================
// Kernel 0: convert Wv fp32 -> fp16
// ============================================================================
__global__ __launch_bounds__(256) void wconv_kernel(const float* __restrict__ Wv)
{
    size_t base = ((size_t)blockIdx.x * 256 + threadIdx.x) * 8;
    float4 x0 = *reinterpret_cast<const float4*>(Wv + base);
    float4 x1 = *reinterpret_cast<const float4*>(Wv + base + 4);
    float xs[8] = {x0.x, x0.y, x0.z, x0.w, x1.x, x1.y, x1.z, x1.w};
    __half h[8];
    #pragma unroll
    for (int j = 0; j < 8; j++) h[j] = __float2half_rn(xs[j]);
    *reinterpret_cast<uint4*>(g_w + base) = *reinterpret_cast<uint4*>(h);
}

// ============================================================================
// Kernel 1: hash + gather -> fp16 e rows.  One block per token.
// ============================================================================
__global__ __launch_bounds__(256) void gather_kernel(
    const int* __restrict__ input_ids,
    const float* __restrict__ tables2,
    const float* __restrict__ tables3)
{
    int t = blockIdx.x;
    int tid = threadIdx.x;
    __shared__ int s_i2, s_i3;
    if (tid == 0) {
        int b = t / TDIM;
        int tt = t % TDIM;
        const int* row = input_ids + (size_t)b * TDIM;
        int id0 = row[tt];
        id0 = id0 < 0 ? 0 : (id0 > VOCAB - 1 ? VOCAB - 1 : id0);
        int s1 = 0, s2 = 0;
        if (tt >= 1) { s1 = row[tt - 1]; s1 = s1 < 0 ? 0 : (s1 > VOCAB - 1 ? VOCAB - 1 : s1); }
        if (tt >= 2) { s2 = row[tt - 2]; s2 = s2 < 0 ? 0 : (s2 > VOCAB - 1 ? VOCAB - 1 : s2); }
        int hash2 = (id0 * M0) ^ (s1 * M1);
        int hash3 = hash2 ^ (s2 * M2);
        int i2 = hash2 % TS; if (i2 < 0) i2 = 0;
        int i3 = hash3 % TS; if (i3 < 0) i3 = 0;
        s_i2 = i2; s_i3 = i3;
    }
    __syncthreads();
    int i2 = s_i2, i3 = s_i3;

    int f0 = tid * 8;
    int seg = f0 >> 8;
    int off = f0 & 255;
    const float* src = (seg < 4)
        ? tables2 + ((size_t)seg * TS + i2) * 256 + off
        : tables3 + ((size_t)(seg - 4) * TS + i3) * 256 + off;
    float4 x0 = *reinterpret_cast<const float4*>(src);
    float4 x1 = *reinterpret_cast<const float4*>(src + 4);
    float xs[8] = {x0.x, x0.y, x0.z, x0.w, x1.x, x1.y, x1.z, x1.w};
    __half h[8];
    #pragma unroll
    for (int j = 0; j < 8; j++) h[j] = __float2half_rn(xs[j]);
    *reinterpret_cast<uint4*>(g_e + (size_t)t * KDIM + f0) =
        *reinterpret_cast<uint4*>(h);
}

// ============================================================================
// Kernel 2: fp16 GEMM via mma.sync (HMMA), fp32 accum in registers.
//   C[m][n] = sum_k e[m][k] * Wv[n][k]   both K-contiguous (NT)
//   CTA tile 128x128, k-chunk 32, 4-stage cp.async pipeline (dist 3).
// Stage (16KB): A @0: 128 rows x 64B (32 fp16); B @8192 same.
//   16B-unit swizzle: c ^= (row>>1)&3.
// ============================================================================
#define NK (KDIM / 32)            // 64 chunks
#define STAGES 4
#define STAGE_BYTES 16384
#define GEMM_SMEM (STAGES * STAGE_BYTES)   // 65536

__global__ __launch_bounds__(256, 1) void gemm_kernel()
{
    extern __shared__ char smem[];
    const uint32_t sbase = smem_to_u32(smem);
    const int tid = threadIdx.x;
    const int lane = tid & 31;
    const int wid = tid >> 5;
    const int warpM = wid & 1;        // 2 warps in M
    const int warpN = wid >> 1;       // 4 warps in N
    const int m0 = blockIdx.y * 128;
    const int n0 = blockIdx.x * 128;

    // ---- per-thread cp.async mapping (4 x 16B per stage) ----
    const __half* src[4];
    uint32_t dstoff[4];
    #pragma unroll
    for (int i = 0; i < 4; i++) {
        int g = tid + i * 256;               // 0..1023
        int isB = g >= 512;
        int gl = g & 511;
        int row = gl >> 2;                   // 0..127
        int ch = gl & 3;                     // 16B unit within 64B row
        const __half* base = isB ? g_w : g_e;
        int rowg = (isB ? n0 : m0) + row;
        src[i] = base + (size_t)rowg * KDIM + ch * 8;
        dstoff[i] = (isB ? 8192u : 0u) + (uint32_t)row * 64u
                  + (uint32_t)((ch ^ ((row >> 1) & 3)) << 4);
    }

    // ---- ldmatrix address components (round-3 verified geometry) ----
    const int l15 = lane & 15;
    const int lhi = lane >> 4;
    const int s = (l15 >> 1) & 3;
    const uint32_t aRowBase = (uint32_t)(warpM * 64 + l15) * 64u;
    const uint32_t bRowBase = (uint32_t)(warpN * 32 + l15) * 64u;
    const uint32_t chj[2] = { (uint32_t)((lhi ^ s) << 4),
                              (uint32_t)(((2 + lhi) ^ s) << 4) };

    float acc[4][4][4];
    #pragma unroll
    for (int mf = 0; mf < 4; mf++)
        #pragma unroll
        for (int nf = 0; nf < 4; nf++)
            #pragma unroll
            for (int q = 0; q < 4; q++) acc[mf][nf][q] = 0.f;

    // ---- prologue: preload stages 0..2 ----
    #pragma unroll
    for (int st = 0; st < 3; st++) {
        uint32_t sb = sbase + st * STAGE_BYTES;
        #pragma unroll
        for (int i = 0; i < 4; i++)
            cp_async16(sb + dstoff[i], src[i] + st * 32);
        cp_commit();
    }

    for (int kt = 0; kt < NK; kt++) {
        if (kt <= NK - 3)      cp_wait_group<2>();
        else if (kt == NK - 2) cp_wait_group<1>();
        else                   cp_wait_group<0>();
        __syncthreads();

        if (kt + 3 < NK) {
            uint32_t sb = sbase + ((kt + 3) & 3) * STAGE_BYTES;
            #pragma unroll
            for (int i = 0; i < 4; i++)
                cp_async16(sb + dstoff[i], src[i] + (kt + 3) * 32);
            cp_commit();
        }

        const uint32_t sb = sbase + (kt & 3) * STAGE_BYTES;
        #pragma unroll
        for (int j = 0; j < 2; j++) {        // two k16 halves of the k32 chunk
            const uint32_t co = chj[j];
            uint32_t a[4][4];
            uint32_t b[2][4];
            #pragma unroll
            for (int mf = 0; mf < 4; mf++)
                ldsm_x4(a[mf], sb + aRowBase + (uint32_t)(mf * 1024) + co);
            #pragma unroll
            for (int nh = 0; nh < 2; nh++)
                ldsm_x4(b[nh], sb + 8192u + bRowBase + (uint32_t)(nh * 1024) + co);

            #pragma unroll
            for (int mf = 0; mf < 4; mf++)
                #pragma unroll
                for (int nf = 0; nf < 4; nf++) {
                    const int nh = nf >> 1, su = nf & 1;
                    mma_f16(acc[mf][nf], a[mf], b[nh][su], b[nh][su + 2]);
                }
        }
    }

    // ---- epilogue: write fp32 result ----
    const int grp = lane >> 2;
    const int q2 = (lane & 3) * 2;
    #pragma unroll
    for (int mf = 0; mf < 4; mf++) {
        #pragma unroll
        for (int nf = 0; nf < 4; nf++) {
            int r = m0 + warpM * 64 + mf * 16 + grp;
            int c = n0 + warpN * 32 + nf * 8 + q2;
            *reinterpret_cast<float2*>(g_v + (size_t)r * DDIM + c) =
                make_float2(acc[mf][nf][0], acc[mf][nf][1]);
            *reinterpret_cast<float2*>(g_v + (size_t)(r + 8) * DDIM + c) =
                make_float2(acc[mf][nf][2], acc[mf][nf][3]);
        }
    }
}

// ============================================================================
// Kernel 3: gating
// ============================================================================
__global__ __launch_bounds__(256) void gate_kernel(
    const float* __restrict__ hidden,
    const float* __restrict__ wh,
    const float* __restrict__ wv,
    float* __restrict__ out)
{
    int t = blockIdx.x;
    int tid = threadIdx.x;
    const float* h = hidden + (size_t)t * DDIM;
    const float* v = g_v + (size_t)t * DDIM;

    float4 v4[2];
    float shh = 0.f, svv = 0.f, shv = 0.f;
    #pragma unroll
    for (int r = 0; r < 2; r++) {
        int q = tid + r * 256;
        float4 h4  = *reinterpret_cast<const float4*>(h + (size_t)q * 4);
        float4 x4  = *reinterpret_cast<const float4*>(v + (size_t)q * 4);
        float4 wh4 = *reinterpret_cast<const float4*>(wh + (size_t)q * 4);
        float4 wv4 = *reinterpret_cast<const float4*>(wv + (size_t)q * 4);
        v4[r] = x4;
        shh += h4.x * h4.x + h4.y * h4.y + h4.z * h4.z + h4.w * h4.w;
        svv += x4.x * x4.x + x4.y * x4.y + x4.z * x4.z + x4.w * x4.w;
        shv += (h4.x * wh4.x) * (x4.x * wv4.x)
             + (h4.y * wh4.y) * (x4.y * wv4.y)
             + (h4.z * wh4.z) * (x4.z * wv4.z)
             + (h4.w * wh4.w) * (x4.w * wv4.w);
    }

    #pragma unroll
    for (int o = 16; o > 0; o >>= 1) {
        shh += __shfl_down_sync(0xffffffffu, shh, o);
        svv += __shfl_down_sync(0xffffffffu, svv, o);
        shv += __shfl_down_sync(0xffffffffu, shv, o);
    }
    __shared__ float s0[8], s1[8], s2[8];
    int warp = tid >> 5, lane = tid & 31;
    if (lane == 0) { s0[warp] = shh; s1[warp] = svv; s2[warp] = shv; }
    __syncthreads();
    float thh = 0.f, tvv = 0.f, thv = 0.f;
    #pragma unroll
    for (int w = 0; w < 8; w++) { thh += s0[w]; tvv += s1[w]; thv += s2[w]; }

    const float eps = 1.1920928955078125e-7f;
    float rh = rsqrtf(thh * (1.f / DDIM) + eps);
    float rv = rsqrtf(tvv * (1.f / DDIM) + eps);
    float gate = thv * rh * rv * (1.f / 45.254833995939045f);
    float ga = fabsf(gate);
    ga = fmaxf(ga, 1e-6f);
    float gs = copysignf(sqrtf(ga), gate);
    float sig = 1.f / (1.f + expf(-gs));

    float* o = out + (size_t)t * DDIM;
    #pragma unroll
    for (int r = 0; r < 2; r++) {
        int q = tid + r * 256;
        float4 x = v4[r];
        x.x *= sig; x.y *= sig; x.z *= sig; x.w *= sig;
        *reinterpret_cast<float4*>(o + (size_t)q * 4) = x;
    }
}

// ---------------------------------------------------------------------------
extern "C" void kernel_launch(void* const* d_in, const int* in_sizes, int n_in,
                              void* d_out, int out_size)
{
    const float* hidden  = (const float*)d_in[0];
    const float* tables2 = (const float*)d_in[1];
    const float* tables3 = (const float*)d_in[2];
    const float* Wv      = (const float*)d_in[3];
    const float* wh      = (const float*)d_in[4];
    const float* wv      = (const float*)d_in[5];
    const int*   ids     = (const int*)d_in[6];
    float* out = (float*)d_out;

    static bool attr_set = false;
    if (!attr_set) {
        cudaFuncSetAttribute(gemm_kernel,
                             cudaFuncAttributeMaxDynamicSharedMemorySize, GEMM_SMEM);
        attr_set = true;
    }

    wconv_kernel<<<(DDIM * KDIM) / (256 * 8), 256>>>(Wv);
    gather_kernel<<<NTOK, 256>>>(ids, tables2, tables3);

    dim3 grid(DDIM / 128, NTOK / 128);   // x = N tiles (share A within a wave)
    gemm_kernel<<<grid, 256, GEMM_SMEM>>>();

    gate_kernel<<<NTOK, 256>>>(hidden, wh, wv, out);
}